// round 6
// baseline (speedup 1.0000x reference)
#include <cuda_runtime.h>
#include <math.h>

// Problem constants
#define Bsz 2
#define Nn  2048
#define Dd  1024
#define Hh  16
#define HDh 64
#define Rr  (Bsz * Nn)          // 4096 rows total

// Scratch (no allocation allowed -> device globals)
__device__ float g_hf[Rr * Dd];        // [4096,1024] per-head value features
__device__ float g_multi[Rr * Dd];     // [4096,1024] fused head outputs
__device__ float g_W12[Dd * Dd];       // out_proj @ o_proj
__device__ float g_Vcat[Dd * Dd];      // vproj repacked [D, H*HD]
__device__ float g_partial[Bsz * 64 * Dd]; // partial column sums for mean
__device__ float g_c[Bsz * Hh * HDh];  // per-(b,head) folded bias

// =========================================================================
// tf32 mma.sync GEMM, 128x128x32 tile, 256 thr (8 warps), N and K fixed 1024.
// SMEM holds tiles in *fragment order*: one LDS.128 per A-frag, LDS.64 per
// B-frag. Register double-buffered global loads. Two independent GEMMs can
// be packed into one launch (blocks0 selects operand set).
// =========================================================================
__device__ __forceinline__ unsigned f2tf32(float v)
{
    unsigned o;
    asm volatile("cvt.rna.tf32.f32 %0, %1;\n" : "=r"(o) : "f"(v));
    return o;
}

__device__ __forceinline__ void mma_tf32(
    float& c0, float& c1, float& c2, float& c3,
    unsigned a0, unsigned a1, unsigned a2, unsigned a3,
    unsigned b0, unsigned b1)
{
    asm volatile(
        "mma.sync.aligned.m16n8k8.row.col.f32.tf32.tf32.f32 "
        "{%0,%1,%2,%3},{%4,%5,%6,%7},{%8,%9},{%0,%1,%2,%3};\n"
        : "+f"(c0), "+f"(c1), "+f"(c2), "+f"(c3)
        : "r"(a0), "r"(a1), "r"(a2), "r"(a3), "r"(b0), "r"(b1));
}

// A: 32 groups (mt 0..7, ks 0..3) of 32 lanes x 4 words, padded 128->132
// B: 64 groups (nt 0..15, ks 0..3) of 32 lanes x 2 words, padded 64->66
#define AGRP 132
#define BGRP 66

__global__ __launch_bounds__(256) void gemm_tf32(
    const float* __restrict__ A0, const float* __restrict__ B0,
    float* __restrict__ C0,
    const float* __restrict__ A1, const float* __restrict__ B1,
    float* __restrict__ C1, int blocks0)
{
    __shared__ __align__(16) unsigned As[32 * AGRP];
    __shared__ __align__(16) unsigned Bs[64 * BGRP];

    const float* A; const float* Bm; float* C; int rb;
    if ((int)blockIdx.x < blocks0) { A = A0; Bm = B0; C = C0; rb = blockIdx.x; }
    else { A = A1; Bm = B1; C = C1; rb = blockIdx.x - blocks0; }

    const int row0 = (rb >> 3) * 128;
    const int col0 = (rb & 7) * 128;

    const int tid    = threadIdx.x;
    const int lane   = tid & 31;
    const int wid    = tid >> 5;
    const int warp_m = wid & 1;          // 64 rows
    const int warp_n = wid >> 1;         // 32 cols

    // ---- precomputed store indices (per thread) ----
    // A loader: element f = i*256+tid, r=f>>3 (row), q=f&7 (k quad)
    // B loader: kr=f>>5 (k), q=f&31 (n quad)
    float4 pa[4], pb[4];

    const float* Arow[4];
    const float* Brow[4];
    int aidx[4], bidx[4];
#pragma unroll
    for (int i = 0; i < 4; i++) {
        int f = i * 256 + tid;
        int r = f >> 3, q = f & 7;
        Arow[i] = A + (long)(row0 + r) * Dd + q * 4;
        int mt = r >> 4, rr = r & 15;
        int rp = rr & 7, hi = rr >> 3;
        int ks = q >> 1, ch = q & 1;
        aidx[i] = ((mt * 4 + ks) * AGRP) + (rp * 4) * 4 + (hi + 2 * ch);
        int kr = f >> 5, qn = f & 31;
        Brow[i] = Bm + (long)kr * Dd + col0 + qn * 4;
        int nt = qn >> 1, g0 = (qn & 1) * 4;
        int ksb = kr >> 3, slotb = (kr >> 2) & 1;
        bidx[i] = ((nt * 4 + ksb) * BGRP) + (g0 * 4 + (kr & 3)) * 2 + slotb;
    }

    float acc[4][4][4];
#pragma unroll
    for (int i = 0; i < 4; i++)
#pragma unroll
        for (int j = 0; j < 4; j++)
#pragma unroll
            for (int q = 0; q < 4; q++) acc[i][j][q] = 0.0f;

    // prefetch k-tile 0
#pragma unroll
    for (int i = 0; i < 4; i++) { pa[i] = *(const float4*)Arow[i];
                                  pb[i] = *(const float4*)Brow[i]; }

    for (int kt = 0; kt < Dd; kt += 32) {
        // ---- store prefetched tile into fragment-order smem ----
#pragma unroll
        for (int i = 0; i < 4; i++) {
            As[aidx[i] + 0]  = f2tf32(pa[i].x);   // lane step = 4 words
            As[aidx[i] + 4]  = f2tf32(pa[i].y);
            As[aidx[i] + 8]  = f2tf32(pa[i].z);
            As[aidx[i] + 12] = f2tf32(pa[i].w);
            Bs[bidx[i] + 0]  = f2tf32(pb[i].x);   // n step = 8 words
            Bs[bidx[i] + 8]  = f2tf32(pb[i].y);
            Bs[bidx[i] + 16] = f2tf32(pb[i].z);
            Bs[bidx[i] + 24] = f2tf32(pb[i].w);
        }
        __syncthreads();

        // ---- prefetch next k-tile while computing this one ----
        // A advances along the row (+k elements); B advances 32 ROWS (+k*Dd).
        if (kt + 32 < Dd) {
#pragma unroll
            for (int i = 0; i < 4; i++) {
                pa[i] = *(const float4*)(Arow[i] + (kt + 32));
                pb[i] = *(const float4*)(Brow[i] + (long)(kt + 32) * Dd);
            }
        }

#pragma unroll
        for (int ks = 0; ks < 4; ks++) {
            uint4 a[4]; uint2 b[4];
#pragma unroll
            for (int mi = 0; mi < 4; mi++)
                a[mi] = *(uint4*)&As[((warp_m * 4 + mi) * 4 + ks) * AGRP + lane * 4];
#pragma unroll
            for (int ni = 0; ni < 4; ni++)
                b[ni] = *(uint2*)&Bs[((warp_n * 4 + ni) * 4 + ks) * BGRP + lane * 2];
#pragma unroll
            for (int mi = 0; mi < 4; mi++)
#pragma unroll
                for (int ni = 0; ni < 4; ni++)
                    mma_tf32(acc[mi][ni][0], acc[mi][ni][1],
                             acc[mi][ni][2], acc[mi][ni][3],
                             a[mi].x, a[mi].y, a[mi].z, a[mi].w,
                             b[ni].x, b[ni].y);
        }
        __syncthreads();
    }

#pragma unroll
    for (int mi = 0; mi < 4; mi++) {
        int r = row0 + warp_m * 64 + mi * 16 + (lane >> 2);
#pragma unroll
        for (int ni = 0; ni < 4; ni++) {
            int c = col0 + warp_n * 32 + ni * 8 + 2 * (lane & 3);
            *(float2*)(C + (long)r * Dd + c) =
                make_float2(acc[mi][ni][0], acc[mi][ni][1]);
            *(float2*)(C + (long)(r + 8) * Dd + c) =
                make_float2(acc[mi][ni][2], acc[mi][ni][3]);
        }
    }
}

// -------------------------------------------------------------------------
// Repack vproj [H][D][HD] -> Vcat [D][H*HD]
// -------------------------------------------------------------------------
__global__ __launch_bounds__(256) void repack_vcat(const float* __restrict__ vproj)
{
    int idx = blockIdx.x * 256 + threadIdx.x;   // 0..2^20-1
    int j = idx & 63;
    int k = (idx >> 6) & 1023;
    int h = idx >> 16;
    g_Vcat[(long)k * Dd + h * HDh + j] = vproj[idx];
}

// -------------------------------------------------------------------------
// Deterministic mean: stage 1, 32-row partial sums. grid (64, B), block 1024.
// -------------------------------------------------------------------------
__global__ __launch_bounds__(1024) void mean_partial_kernel()
{
    int j  = threadIdx.x;
    int nc = blockIdx.x;
    int b  = blockIdx.y;
    const float* base = g_hf + ((long)b * Nn + nc * 32) * Dd + j;
    float s = 0.0f;
#pragma unroll 8
    for (int n = 0; n < 32; n++) s += base[(long)n * Dd];
    g_partial[((long)b * 64 + nc) * Dd + j] = s;
}

// -------------------------------------------------------------------------
// c[b,h,k] = fus_b1[h,k] + sum_m mean[b,h,m] * (w1[h,64+m,k] + w1[h,128+m,k])
// -------------------------------------------------------------------------
__global__ __launch_bounds__(64) void compute_c_kernel(
    const float* __restrict__ fus_w1, const float* __restrict__ fus_b1)
{
    int hi = blockIdx.x, b = blockIdx.y, k = threadIdx.x;
    __shared__ float mean_s[HDh];

    float s = 0.0f;
    for (int nc = 0; nc < 64; nc++)
        s += g_partial[((long)b * 64 + nc) * Dd + hi * HDh + k];
    mean_s[k] = s * (1.0f / (float)Nn);
    __syncthreads();

    const float* w1 = fus_w1 + (long)hi * 192 * HDh;
    float acc = fus_b1[hi * HDh + k];
#pragma unroll 8
    for (int m = 0; m < HDh; m++)
        acc += mean_s[m] * (w1[(64 + m) * HDh + k] + w1[(128 + m) * HDh + k]);
    g_c[((long)b * Hh + hi) * HDh + k] = acc;
}

__device__ __forceinline__ float gelu_exact(float x)
{
    return 0.5f * x * (1.0f + erff(x * 0.70710678118654752440f));
}

// -------------------------------------------------------------------------
// Fused per-head relation MLP, register-tiled 4x4 (64 rows x 64 cols/block)
// -------------------------------------------------------------------------
__global__ __launch_bounds__(256) void fusion_kernel(
    const float* __restrict__ fus_w1, const float* __restrict__ fus_w2,
    const float* __restrict__ fus_b2)
{
    __shared__ float hfs[HDh][HDh];
    __shared__ float w1s[HDh][HDh];   // reused as t after first layer
    __shared__ float w2s[HDh][HDh];

    const int hi = blockIdx.y;
    const int r0 = blockIdx.x * 64;
    const int b  = r0 / Nn;
    const int tid = threadIdx.x;
    const int tr = tid >> 4;          // 0..15, 4 rows each
    const int tc = tid & 15;          // 0..15, 4 cols each

    const float* w1 = fus_w1 + (long)hi * 192 * HDh;  // first 64 rows used
    const float* w2 = fus_w2 + (long)hi * HDh * HDh;

#pragma unroll
    for (int i = 0; i < 4; i++) {
        int f = i * 256 + tid;        // float4 index 0..1023
        int m = f >> 4, q = f & 15;
        *(float4*)&w1s[m][q * 4] = *(const float4*)(w1 + m * 64 + q * 4);
        *(float4*)&w2s[m][q * 4] = *(const float4*)(w2 + m * 64 + q * 4);
        int rl = f >> 4;
        *(float4*)&hfs[rl][q * 4] =
            *(const float4*)(g_hf + (long)(r0 + rl) * Dd + hi * HDh + q * 4);
    }
    float cv[4], b2v[4];
#pragma unroll
    for (int j = 0; j < 4; j++) {
        cv[j]  = g_c[((long)b * Hh + hi) * HDh + tc * 4 + j];
        b2v[j] = fus_b2[hi * HDh + tc * 4 + j];
    }
    __syncthreads();

    float acc[4][4];
#pragma unroll
    for (int i = 0; i < 4; i++)
#pragma unroll
        for (int j = 0; j < 4; j++) acc[i][j] = cv[j];

#pragma unroll 4
    for (int m = 0; m < HDh; m++) {
        float4 wv = *(float4*)&w1s[m][tc * 4];
        float hv[4];
#pragma unroll
        for (int i = 0; i < 4; i++) hv[i] = hfs[tr * 4 + i][m];
#pragma unroll
        for (int i = 0; i < 4; i++) {
            acc[i][0] += hv[i] * wv.x;
            acc[i][1] += hv[i] * wv.y;
            acc[i][2] += hv[i] * wv.z;
            acc[i][3] += hv[i] * wv.w;
        }
    }
    __syncthreads();   // everyone done reading w1s
#pragma unroll
    for (int i = 0; i < 4; i++)
#pragma unroll
        for (int j = 0; j < 4; j++)
            w1s[tr * 4 + i][tc * 4 + j] = gelu_exact(acc[i][j]);
    __syncthreads();

    float acc2[4][4];
#pragma unroll
    for (int i = 0; i < 4; i++)
#pragma unroll
        for (int j = 0; j < 4; j++) acc2[i][j] = b2v[j];

#pragma unroll 4
    for (int m = 0; m < HDh; m++) {
        float4 wv = *(float4*)&w2s[m][tc * 4];
        float tv[4];
#pragma unroll
        for (int i = 0; i < 4; i++) tv[i] = w1s[tr * 4 + i][m];
#pragma unroll
        for (int i = 0; i < 4; i++) {
            acc2[i][0] += tv[i] * wv.x;
            acc2[i][1] += tv[i] * wv.y;
            acc2[i][2] += tv[i] * wv.z;
            acc2[i][3] += tv[i] * wv.w;
        }
    }
#pragma unroll
    for (int i = 0; i < 4; i++) {
        float4 v = make_float4(acc2[i][0], acc2[i][1], acc2[i][2], acc2[i][3]);
        *(float4*)(g_multi + (long)(r0 + tr * 4 + i) * Dd + hi * HDh + tc * 4) = v;
    }
}

// -------------------------------------------------------------------------
// Tail outputs (constants), only if the output buffer carries them.
// -------------------------------------------------------------------------
__global__ void tail_kernel(float* __restrict__ out, int out_size)
{
    const int base = Rr * Dd;
    int i = blockIdx.x * blockDim.x + threadIdx.x;
    if (out_size >= base + 2 * Rr) {
        float strength = 1.0f - logf(1.0f / (float)Nn + 1e-8f);
        if (i < Rr)            out[base + i] = 1023.0f;
        else if (i < 2 * Rr)   out[base + i] = strength;
    }
}

// -------------------------------------------------------------------------
extern "C" void kernel_launch(void* const* d_in, const int* in_sizes, int n_in,
                              void* d_out, int out_size)
{
    const float* h         = (const float*)d_in[0];
    // d_in[1..8]: fe/be scorer weights -> provably dead (uniform softmax)
    const float* vproj_w   = (const float*)d_in[9];
    const float* fus_w1    = (const float*)d_in[10];
    const float* fus_b1    = (const float*)d_in[11];
    const float* fus_w2    = (const float*)d_in[12];
    const float* fus_b2    = (const float*)d_in[13];
    const float* out_proj  = (const float*)d_in[14];
    const float* o_proj    = (const float*)d_in[15];
    float* z = (float*)d_out;

    float *hf_p, *multi_p, *W12_p, *vcat_p;
    cudaGetSymbolAddress((void**)&hf_p,    g_hf);
    cudaGetSymbolAddress((void**)&multi_p, g_multi);
    cudaGetSymbolAddress((void**)&W12_p,   g_W12);
    cudaGetSymbolAddress((void**)&vcat_p,  g_Vcat);

    // 0) repack vproj into contiguous [D, D]
    repack_vcat<<<(Dd * Dd) / 256, 256>>>(vproj_w);

    // 1+2) hf = h @ Vcat  AND  W12 = out_proj @ o_proj, one packed launch
    //      op0: 4096x1024 -> 32*8 = 256 blocks; op1: 1024x1024 -> 64 blocks
    gemm_tf32<<<320, 256>>>(h, vcat_p, hf_p, out_proj, o_proj, W12_p, 256);

    // 3) deterministic mean over sequence + folded bias c
    {
        dim3 grid(64, Bsz);
        mean_partial_kernel<<<grid, 1024>>>();
        dim3 gridc(Hh, Bsz);
        compute_c_kernel<<<gridc, 64>>>(fus_w1, fus_b1);
    }
    // 4) fused per-head relation MLP -> multi
    {
        dim3 grid(Rr / 64, Hh);
        fusion_kernel<<<grid, 256>>>(fus_w1, fus_w2, fus_b2);
    }
    // 5) z = multi @ W12   (writes directly into d_out)
    gemm_tf32<<<256, 256>>>(multi_p, W12_p, z, multi_p, W12_p, z, 256);

    // 6) constant tail outputs
    tail_kernel<<<32, 256>>>(z, out_size);
}

// round 7
// speedup vs baseline: 1.1886x; 1.1886x over previous
#include <cuda_runtime.h>
#include <math.h>

// Problem constants
#define Bsz 2
#define Nn  2048
#define Dd  1024
#define Hh  16
#define HDh 64
#define Rr  (Bsz * Nn)          // 4096 rows total

// Scratch (no allocation allowed -> device globals)
__device__ float g_hf[Rr * Dd];        // [4096,1024] per-head value features
__device__ float g_multi[Rr * Dd];     // [4096,1024] fused head outputs
__device__ float g_W12[Dd * Dd];       // out_proj @ o_proj
__device__ float g_Vcat[Dd * Dd];      // vproj repacked [D, H*HD]
__device__ float g_partial[Bsz * 64 * Dd]; // partial column sums for mean
__device__ float g_c[Bsz * Hh * HDh];  // per-(b,head) folded bias

// =========================================================================
// tf32 mma.sync GEMM, 128x128x32 tile, 256 thr (8 warps), N and K fixed 1024.
// Fragment-order SMEM (LDS.128 per A-frag, LDS.64 per B-frag), register
// prefetch of the next k-tile, and a TWO-STAGE smem buffer so only ONE
// __syncthreads per k-iteration is needed (write i+2 vs read i is ordered
// through the barrier at i+1). Dynamic smem: 2 * (32*AGRP + 64*BGRP) words.
// =========================================================================
__device__ __forceinline__ unsigned f2tf32(float v)
{
    unsigned o;
    asm volatile("cvt.rna.tf32.f32 %0, %1;\n" : "=r"(o) : "f"(v));
    return o;
}

__device__ __forceinline__ void mma_tf32(
    float& c0, float& c1, float& c2, float& c3,
    unsigned a0, unsigned a1, unsigned a2, unsigned a3,
    unsigned b0, unsigned b1)
{
    asm volatile(
        "mma.sync.aligned.m16n8k8.row.col.f32.tf32.tf32.f32 "
        "{%0,%1,%2,%3},{%4,%5,%6,%7},{%8,%9},{%0,%1,%2,%3};\n"
        : "+f"(c0), "+f"(c1), "+f"(c2), "+f"(c3)
        : "r"(a0), "r"(a1), "r"(a2), "r"(a3), "r"(b0), "r"(b1));
}

// A: 32 groups (mt 0..7, ks 0..3) of 32 lanes x 4 words, padded 128->132
// B: 64 groups (nt 0..15, ks 0..3) of 32 lanes x 2 words, padded 64->66
#define AGRP 132
#define BGRP 66
#define STGW (32 * AGRP + 64 * BGRP)     // words per stage = 8448
#define GEMM_SMEM_BYTES (2 * STGW * 4)   // 67584

extern __shared__ unsigned dynsmem[];

__global__ __launch_bounds__(256) void gemm_tf32(
    const float* __restrict__ A0, const float* __restrict__ B0,
    float* __restrict__ C0,
    const float* __restrict__ A1, const float* __restrict__ B1,
    float* __restrict__ C1, int blocks0)
{
    const float* A; const float* Bm; float* C; int rb;
    if ((int)blockIdx.x < blocks0) { A = A0; Bm = B0; C = C0; rb = blockIdx.x; }
    else { A = A1; Bm = B1; C = C1; rb = blockIdx.x - blocks0; }

    const int row0 = (rb >> 3) * 128;
    const int col0 = (rb & 7) * 128;

    const int tid    = threadIdx.x;
    const int lane   = tid & 31;
    const int wid    = tid >> 5;
    const int warp_m = wid & 1;          // 64 rows
    const int warp_n = wid >> 1;         // 32 cols

    // ---- precomputed store indices (stage-relative) ----
    float4 pa[4], pb[4];
    const float* Arow[4];
    const float* Brow[4];
    int aidx[4], bidx[4];
#pragma unroll
    for (int i = 0; i < 4; i++) {
        int f = i * 256 + tid;
        int r = f >> 3, q = f & 7;
        Arow[i] = A + (long)(row0 + r) * Dd + q * 4;
        int mt = r >> 4, rr = r & 15;
        int rp = rr & 7, hi = rr >> 3;
        int ks = q >> 1, ch = q & 1;
        aidx[i] = ((mt * 4 + ks) * AGRP) + (rp * 4) * 4 + (hi + 2 * ch);
        int kr = f >> 5, qn = f & 31;
        Brow[i] = Bm + (long)kr * Dd + col0 + qn * 4;
        int nt = qn >> 1, g0 = (qn & 1) * 4;
        int ksb = kr >> 3, slotb = (kr >> 2) & 1;
        bidx[i] = 32 * AGRP + ((nt * 4 + ksb) * BGRP) + (g0 * 4 + (kr & 3)) * 2 + slotb;
    }

    float acc[4][4][4];
#pragma unroll
    for (int i = 0; i < 4; i++)
#pragma unroll
        for (int j = 0; j < 4; j++)
#pragma unroll
            for (int q = 0; q < 4; q++) acc[i][j][q] = 0.0f;

    // prefetch k-tile 0
#pragma unroll
    for (int i = 0; i < 4; i++) { pa[i] = *(const float4*)Arow[i];
                                  pb[i] = *(const float4*)Brow[i]; }

    for (int it = 0; it < 32; it++) {
        unsigned* S = dynsmem + (it & 1) * STGW;

        // ---- store prefetched tile into fragment-order smem (this stage) ----
#pragma unroll
        for (int i = 0; i < 4; i++) {
            S[aidx[i] + 0]  = f2tf32(pa[i].x);
            S[aidx[i] + 4]  = f2tf32(pa[i].y);
            S[aidx[i] + 8]  = f2tf32(pa[i].z);
            S[aidx[i] + 12] = f2tf32(pa[i].w);
            S[bidx[i] + 0]  = f2tf32(pb[i].x);
            S[bidx[i] + 8]  = f2tf32(pb[i].y);
            S[bidx[i] + 16] = f2tf32(pb[i].z);
            S[bidx[i] + 24] = f2tf32(pb[i].w);
        }

        // ---- prefetch next k-tile (A: +k elems; B: +k rows) ----
        if (it < 31) {
            int kn = (it + 1) * 32;
#pragma unroll
            for (int i = 0; i < 4; i++) {
                pa[i] = *(const float4*)(Arow[i] + kn);
                pb[i] = *(const float4*)(Brow[i] + (long)kn * Dd);
            }
        }

        __syncthreads();   // single barrier per iteration (2-stage buffer)

        const unsigned* Sa = S;
#pragma unroll
        for (int ks = 0; ks < 4; ks++) {
            uint4 a[4]; uint2 b[4];
#pragma unroll
            for (int mi = 0; mi < 4; mi++)
                a[mi] = *(const uint4*)&Sa[((warp_m * 4 + mi) * 4 + ks) * AGRP + lane * 4];
#pragma unroll
            for (int ni = 0; ni < 4; ni++)
                b[ni] = *(const uint2*)&Sa[32 * AGRP + ((warp_n * 4 + ni) * 4 + ks) * BGRP + lane * 2];
#pragma unroll
            for (int mi = 0; mi < 4; mi++)
#pragma unroll
                for (int ni = 0; ni < 4; ni++)
                    mma_tf32(acc[mi][ni][0], acc[mi][ni][1],
                             acc[mi][ni][2], acc[mi][ni][3],
                             a[mi].x, a[mi].y, a[mi].z, a[mi].w,
                             b[ni].x, b[ni].y);
        }
        // no trailing sync: next iteration writes the OTHER stage
    }

#pragma unroll
    for (int mi = 0; mi < 4; mi++) {
        int r = row0 + warp_m * 64 + mi * 16 + (lane >> 2);
#pragma unroll
        for (int ni = 0; ni < 4; ni++) {
            int c = col0 + warp_n * 32 + ni * 8 + 2 * (lane & 3);
            *(float2*)(C + (long)r * Dd + c) =
                make_float2(acc[mi][ni][0], acc[mi][ni][1]);
            *(float2*)(C + (long)(r + 8) * Dd + c) =
                make_float2(acc[mi][ni][2], acc[mi][ni][3]);
        }
    }
}

// -------------------------------------------------------------------------
// Repack vproj [H][D][HD] -> Vcat [D][H*HD]
// -------------------------------------------------------------------------
__global__ __launch_bounds__(256) void repack_vcat(const float* __restrict__ vproj)
{
    int idx = blockIdx.x * 256 + threadIdx.x;   // 0..2^20-1
    int j = idx & 63;
    int k = (idx >> 6) & 1023;
    int h = idx >> 16;
    g_Vcat[(long)k * Dd + h * HDh + j] = vproj[idx];
}

// -------------------------------------------------------------------------
// Deterministic mean: stage 1, 32-row partial sums. grid (64, B), block 1024.
// -------------------------------------------------------------------------
__global__ __launch_bounds__(1024) void mean_partial_kernel()
{
    int j  = threadIdx.x;
    int nc = blockIdx.x;
    int b  = blockIdx.y;
    const float* base = g_hf + ((long)b * Nn + nc * 32) * Dd + j;
    float s = 0.0f;
#pragma unroll 8
    for (int n = 0; n < 32; n++) s += base[(long)n * Dd];
    g_partial[((long)b * 64 + nc) * Dd + j] = s;
}

// -------------------------------------------------------------------------
// c[b,h,k] = fus_b1[h,k] + sum_m mean[b,h,m] * (w1[h,64+m,k] + w1[h,128+m,k])
// Block 256 = 64 k-lanes x 4 m-groups; deterministic fixed-order reduction.
// -------------------------------------------------------------------------
__global__ __launch_bounds__(256) void compute_c_kernel(
    const float* __restrict__ fus_w1, const float* __restrict__ fus_b1)
{
    int hi = blockIdx.x, b = blockIdx.y;
    int k = threadIdx.x & 63;
    int g = threadIdx.x >> 6;           // 0..3
    __shared__ float mean_s[HDh];
    __shared__ float part[4][HDh];
    __shared__ float part2[4][HDh];

    // mean over 64 partial chunks, split 16 per group (fixed order)
    float s = 0.0f;
    for (int nc = g * 16; nc < g * 16 + 16; nc++)
        s += g_partial[((long)b * 64 + nc) * Dd + hi * HDh + k];
    part[g][k] = s;
    __syncthreads();
    if (g == 0) {
        float m = ((part[0][k] + part[1][k]) + part[2][k]) + part[3][k];
        mean_s[k] = m * (1.0f / (float)Nn);
    }
    __syncthreads();

    const float* w1 = fus_w1 + (long)hi * 192 * HDh;
    float acc = 0.0f;
#pragma unroll 4
    for (int m = g * 16; m < g * 16 + 16; m++)
        acc += mean_s[m] * (w1[(64 + m) * HDh + k] + w1[(128 + m) * HDh + k]);
    part2[g][k] = acc;
    __syncthreads();
    if (g == 0) {
        float v = fus_b1[hi * HDh + k]
                + ((part2[0][k] + part2[1][k]) + part2[2][k]) + part2[3][k];
        g_c[((long)b * Hh + hi) * HDh + k] = v;
    }
}

__device__ __forceinline__ float gelu_exact(float x)
{
    return 0.5f * x * (1.0f + erff(x * 0.70710678118654752440f));
}

// -------------------------------------------------------------------------
// Fused per-head relation MLP, register-tiled 4x4 (64 rows x 64 cols/block)
// -------------------------------------------------------------------------
__global__ __launch_bounds__(256) void fusion_kernel(
    const float* __restrict__ fus_w1, const float* __restrict__ fus_w2,
    const float* __restrict__ fus_b2)
{
    __shared__ float hfs[HDh][HDh];
    __shared__ float w1s[HDh][HDh];   // reused as t after first layer
    __shared__ float w2s[HDh][HDh];

    const int hi = blockIdx.y;
    const int r0 = blockIdx.x * 64;
    const int b  = r0 / Nn;
    const int tid = threadIdx.x;
    const int tr = tid >> 4;          // 0..15, 4 rows each
    const int tc = tid & 15;          // 0..15, 4 cols each

    const float* w1 = fus_w1 + (long)hi * 192 * HDh;  // first 64 rows used
    const float* w2 = fus_w2 + (long)hi * HDh * HDh;

#pragma unroll
    for (int i = 0; i < 4; i++) {
        int f = i * 256 + tid;        // float4 index 0..1023
        int m = f >> 4, q = f & 15;
        *(float4*)&w1s[m][q * 4] = *(const float4*)(w1 + m * 64 + q * 4);
        *(float4*)&w2s[m][q * 4] = *(const float4*)(w2 + m * 64 + q * 4);
        int rl = f >> 4;
        *(float4*)&hfs[rl][q * 4] =
            *(const float4*)(g_hf + (long)(r0 + rl) * Dd + hi * HDh + q * 4);
    }
    float cv[4], b2v[4];
#pragma unroll
    for (int j = 0; j < 4; j++) {
        cv[j]  = g_c[((long)b * Hh + hi) * HDh + tc * 4 + j];
        b2v[j] = fus_b2[hi * HDh + tc * 4 + j];
    }
    __syncthreads();

    float acc[4][4];
#pragma unroll
    for (int i = 0; i < 4; i++)
#pragma unroll
        for (int j = 0; j < 4; j++) acc[i][j] = cv[j];

#pragma unroll 4
    for (int m = 0; m < HDh; m++) {
        float4 wv = *(float4*)&w1s[m][tc * 4];
        float hv[4];
#pragma unroll
        for (int i = 0; i < 4; i++) hv[i] = hfs[tr * 4 + i][m];
#pragma unroll
        for (int i = 0; i < 4; i++) {
            acc[i][0] += hv[i] * wv.x;
            acc[i][1] += hv[i] * wv.y;
            acc[i][2] += hv[i] * wv.z;
            acc[i][3] += hv[i] * wv.w;
        }
    }
    __syncthreads();   // everyone done reading w1s
#pragma unroll
    for (int i = 0; i < 4; i++)
#pragma unroll
        for (int j = 0; j < 4; j++)
            w1s[tr * 4 + i][tc * 4 + j] = gelu_exact(acc[i][j]);
    __syncthreads();

    float acc2[4][4];
#pragma unroll
    for (int i = 0; i < 4; i++)
#pragma unroll
        for (int j = 0; j < 4; j++) acc2[i][j] = b2v[j];

#pragma unroll 4
    for (int m = 0; m < HDh; m++) {
        float4 wv = *(float4*)&w2s[m][tc * 4];
        float tv[4];
#pragma unroll
        for (int i = 0; i < 4; i++) tv[i] = w1s[tr * 4 + i][m];
#pragma unroll
        for (int i = 0; i < 4; i++) {
            acc2[i][0] += tv[i] * wv.x;
            acc2[i][1] += tv[i] * wv.y;
            acc2[i][2] += tv[i] * wv.z;
            acc2[i][3] += tv[i] * wv.w;
        }
    }
#pragma unroll
    for (int i = 0; i < 4; i++) {
        float4 v = make_float4(acc2[i][0], acc2[i][1], acc2[i][2], acc2[i][3]);
        *(float4*)(g_multi + (long)(r0 + tr * 4 + i) * Dd + hi * HDh + tc * 4) = v;
    }
}

// -------------------------------------------------------------------------
// Tail outputs (constants), only if the output buffer carries them.
// -------------------------------------------------------------------------
__global__ void tail_kernel(float* __restrict__ out, int out_size)
{
    const int base = Rr * Dd;
    int i = blockIdx.x * blockDim.x + threadIdx.x;
    if (out_size >= base + 2 * Rr) {
        float strength = 1.0f - logf(1.0f / (float)Nn + 1e-8f);
        if (i < Rr)            out[base + i] = 1023.0f;
        else if (i < 2 * Rr)   out[base + i] = strength;
    }
}

// -------------------------------------------------------------------------
extern "C" void kernel_launch(void* const* d_in, const int* in_sizes, int n_in,
                              void* d_out, int out_size)
{
    const float* h         = (const float*)d_in[0];
    // d_in[1..8]: fe/be scorer weights -> provably dead (uniform softmax)
    const float* vproj_w   = (const float*)d_in[9];
    const float* fus_w1    = (const float*)d_in[10];
    const float* fus_b1    = (const float*)d_in[11];
    const float* fus_w2    = (const float*)d_in[12];
    const float* fus_b2    = (const float*)d_in[13];
    const float* out_proj  = (const float*)d_in[14];
    const float* o_proj    = (const float*)d_in[15];
    float* z = (float*)d_out;

    float *hf_p, *multi_p, *W12_p, *vcat_p;
    cudaGetSymbolAddress((void**)&hf_p,    g_hf);
    cudaGetSymbolAddress((void**)&multi_p, g_multi);
    cudaGetSymbolAddress((void**)&W12_p,   g_W12);
    cudaGetSymbolAddress((void**)&vcat_p,  g_Vcat);

    // opt in to >48KB dynamic smem (idempotent, host-side attribute)
    static int smem_set = 0;
    if (!smem_set) {
        cudaFuncSetAttribute(gemm_tf32,
                             cudaFuncAttributeMaxDynamicSharedMemorySize,
                             GEMM_SMEM_BYTES);
        smem_set = 1;
    }

    // 0) repack vproj into contiguous [D, D]
    repack_vcat<<<(Dd * Dd) / 256, 256>>>(vproj_w);

    // 1+2) hf = h @ Vcat  AND  W12 = out_proj @ o_proj, one packed launch
    gemm_tf32<<<320, 256, GEMM_SMEM_BYTES>>>(h, vcat_p, hf_p,
                                             out_proj, o_proj, W12_p, 256);

    // 3) deterministic mean over sequence + folded bias c
    {
        dim3 grid(64, Bsz);
        mean_partial_kernel<<<grid, 1024>>>();
        dim3 gridc(Hh, Bsz);
        compute_c_kernel<<<gridc, 256>>>(fus_w1, fus_b1);
    }
    // 4) fused per-head relation MLP -> multi
    {
        dim3 grid(Rr / 64, Hh);
        fusion_kernel<<<grid, 256>>>(fus_w1, fus_w2, fus_b2);
    }
    // 5) z = multi @ W12   (writes directly into d_out)
    gemm_tf32<<<256, 256, GEMM_SMEM_BYTES>>>(multi_p, W12_p, z,
                                             multi_p, W12_p, z, 256);

    // 6) constant tail outputs
    tail_kernel<<<32, 256>>>(z, out_size);
}